// round 2
// baseline (speedup 1.0000x reference)
#include <cuda_runtime.h>

#define D 128
#define NMAX 50000

// ---- scratch (static device globals; no allocations allowed) ----
__device__ float g_A  [(size_t)NMAX * D];   // h @ W1a.T
__device__ float g_B  [(size_t)NMAX * D];   // h @ W1b.T
__device__ float g_agg[(size_t)NMAX * D];   // scatter-add target
__device__ float g_T  [(size_t)NMAX * D];   // silu(u_in @ U1.T + c1)
__device__ int   g_is64;                    // edge_index dtype flag

__device__ __forceinline__ float silu_f(float v) {
    return v / (1.0f + __expf(-v));
}

// ----------------------------------------------------------------------------
// Detect whether edge_index is int64 or int32. For int64 (values < 2^31),
// every odd 32-bit word is the zero high half. For int32 random indices,
// odd words are real indices — over 1024 samples at least one is nonzero.
// ----------------------------------------------------------------------------
__global__ void detect_idx_kernel(const int* __restrict__ ei32, int E)
{
    __shared__ int any_nz;
    if (threadIdx.x == 0) any_nz = 0;
    __syncthreads();
    int samples = min(1024, E);
    for (int i = threadIdx.x; i < samples; i += blockDim.x)
        if (ei32[2 * i + 1] != 0) any_nz = 1;
    __syncthreads();
    if (threadIdx.x == 0) g_is64 = (any_nz == 0) ? 1 : 0;
}

__device__ __forceinline__ void load_edge(const void* ei, int E, int e, int is64,
                                          int& s, int& r)
{
    if (is64) {
        s = (int)((const long long*)ei)[e];
        r = (int)((const long long*)ei)[(size_t)E + e];
    } else {
        s = ((const int*)ei)[e];
        r = ((const int*)ei)[E + e];
    }
}

// ----------------------------------------------------------------------------
// 8x8 register-tiled fp32 GEMM core over a [ER x 128] activation tile (row-major,
// padded stride 132) and a [128 x 128] weight tile stored k-major (WT[k][d],
// stride 132). Thread (tx,ty) owns rows {ty*4..+3, ER/2+ty*4..+3} and cols
// {tx*4..+3, 64+tx*4..+3}. x-reads are 2-address warp broadcasts; w-reads are
// aligned float4 (132*4 = 528 = 33*16).
// ----------------------------------------------------------------------------
template<int ER>
__device__ __forceinline__ void gemm_tile(const float (*__restrict__ XE)[132],
                                          const float (*__restrict__ WT)[132],
                                          float (&acc)[8][8], int tx, int ty)
{
    const int eb = ty * 4, db = tx * 4;
    #pragma unroll 4
    for (int k = 0; k < 128; ++k) {
        float xa[8];
        #pragma unroll
        for (int i = 0; i < 4; ++i) {
            xa[i]     = XE[eb + i][k];
            xa[4 + i] = XE[ER / 2 + eb + i][k];
        }
        float4 w0 = *(const float4*)&WT[k][db];
        float4 w1 = *(const float4*)&WT[k][64 + db];
        float wv[8] = {w0.x, w0.y, w0.z, w0.w, w1.x, w1.y, w1.z, w1.w};
        #pragma unroll
        for (int i = 0; i < 8; ++i)
            #pragma unroll
            for (int j = 0; j < 8; ++j)
                acc[i][j] = fmaf(xa[i], wv[j], acc[i][j]);
    }
}

// ----------------------------------------------------------------------------
__global__ void zero_agg_kernel(int n4) {
    int i = blockIdx.x * blockDim.x + threadIdx.x;
    if (i < n4) ((float4*)g_agg)[i] = make_float4(0.f, 0.f, 0.f, 0.f);
}

// ----------------------------------------------------------------------------
// A = h @ W1[:, :128].T ; B = h @ W1[:, 128:256].T   (blockIdx.y selects half)
// W1 is [128, 257] row-major.
// ----------------------------------------------------------------------------
__global__ __launch_bounds__(256, 1)
void nodeAB_kernel(const float* __restrict__ h, const float* __restrict__ W1, int N)
{
    extern __shared__ float sm[];
    float (*XE)[132] = (float (*)[132])sm;                 // 128 x 132
    float (*WT)[132] = (float (*)[132])(sm + 128 * 132);   // 128 x 132

    const int tid  = threadIdx.x;
    const int n0   = blockIdx.x * 128;
    const int half = blockIdx.y;

    for (int i = tid; i < 128 * 128; i += 256) {
        int d = i >> 7, k = i & 127;
        WT[k][d] = W1[d * 257 + half * 128 + k];
    }
    for (int i = tid; i < 128 * 32; i += 256) {
        int e = i >> 5, d4 = (i & 31) << 2;
        int n = n0 + e;
        float4 v = make_float4(0.f, 0.f, 0.f, 0.f);
        if (n < N) v = *(const float4*)(h + (size_t)n * D + d4);
        *(float4*)&XE[e][d4] = v;
    }
    __syncthreads();

    const int tx = tid & 15, ty = tid >> 4;
    float acc[8][8];
    #pragma unroll
    for (int i = 0; i < 8; ++i)
        #pragma unroll
        for (int j = 0; j < 8; ++j) acc[i][j] = 0.f;

    gemm_tile<128>(XE, WT, acc, tx, ty);

    float* out = half ? g_B : g_A;
    #pragma unroll
    for (int i = 0; i < 8; ++i) {
        int e = (i < 4) ? (ty * 4 + i) : (64 + ty * 4 + i - 4);
        int n = n0 + e;
        if (n >= N) continue;
        float4 v0 = make_float4(acc[i][0], acc[i][1], acc[i][2], acc[i][3]);
        float4 v1 = make_float4(acc[i][4], acc[i][5], acc[i][6], acc[i][7]);
        *(float4*)(out + (size_t)n * D + tx * 4)      = v0;
        *(float4*)(out + (size_t)n * D + 64 + tx * 4) = v1;
    }
}

// ----------------------------------------------------------------------------
// Edge kernel: per 256-edge tile,
//   x[e] = silu(A[s] + B[r] + dist*w1c + b1)      (layer-1 collapsed)
//   y[e] = silu(x[e] @ W2.T + b2)                  (8x8-tiled GEMM)
//   atomicAdd(agg[r], y[e])
// ----------------------------------------------------------------------------
__global__ __launch_bounds__(512, 1)
void edge_kernel(const float* __restrict__ coords,
                 const void* __restrict__ ei,
                 const float* __restrict__ W1,
                 const float* __restrict__ b1,
                 const float* __restrict__ W2,
                 const float* __restrict__ b2,
                 int E)
{
    extern __shared__ float sm[];
    float (*XE)[132] = (float (*)[132])sm;                       // 256 x 132
    float (*WT)[132] = (float (*)[132])(sm + 256 * 132);         // 128 x 132
    float* sw1c  = sm + 256 * 132 + 128 * 132;                   // 128
    float* sb1   = sw1c + 128;                                   // 128
    float* sb2   = sb1 + 128;                                    // 128
    float* sdist = sb2 + 128;                                    // 256
    int*   sr    = (int*)(sdist + 256);                          // 256
    int*   ss    = sr + 256;                                     // 256

    const int tid = threadIdx.x;
    const int e0  = blockIdx.x * 256;
    const int is64 = g_is64;

    // stage W2 k-major
    for (int i = tid; i < 128 * 128; i += 512) {
        int d = i >> 7, k = i & 127;
        WT[k][d] = W2[i];
    }
    if (tid < 128) {
        sb1[tid]  = b1[tid];
        sb2[tid]  = b2[tid];
        sw1c[tid] = W1[tid * 257 + 256];
    }
    if (tid < 256) {
        int e = e0 + tid;
        if (e < E) {
            int s, r;
            load_edge(ei, E, e, is64, s, r);
            ss[tid] = s;
            sr[tid] = r;
            float dx = coords[s * 3 + 0] - coords[r * 3 + 0];
            float dy = coords[s * 3 + 1] - coords[r * 3 + 1];
            float dz = coords[s * 3 + 2] - coords[r * 3 + 2];
            sdist[tid] = sqrtf(dx * dx + dy * dy + dz * dz);
        } else {
            ss[tid] = 0; sr[tid] = -1; sdist[tid] = 0.f;
        }
    }
    __syncthreads();

    // stage 1: gather + collapsed layer-1 + silu
    for (int i = tid; i < 256 * 32; i += 512) {
        int e = i >> 5, d4 = (i & 31) << 2;
        int rr = sr[e]; if (rr < 0) rr = 0;
        const float4 a = *(const float4*)(g_A + (size_t)ss[e] * D + d4);
        const float4 b = *(const float4*)(g_B + (size_t)rr    * D + d4);
        float dist = sdist[e];
        float4 o;
        o.x = silu_f(a.x + b.x + dist * sw1c[d4 + 0] + sb1[d4 + 0]);
        o.y = silu_f(a.y + b.y + dist * sw1c[d4 + 1] + sb1[d4 + 1]);
        o.z = silu_f(a.z + b.z + dist * sw1c[d4 + 2] + sb1[d4 + 2]);
        o.w = silu_f(a.w + b.w + dist * sw1c[d4 + 3] + sb1[d4 + 3]);
        *(float4*)&XE[e][d4] = o;
    }
    __syncthreads();

    // stage 2: layer-2 GEMM
    const int tx = tid & 15, ty = tid >> 4;
    float acc[8][8];
    #pragma unroll
    for (int i = 0; i < 8; ++i)
        #pragma unroll
        for (int j = 0; j < 8; ++j) acc[i][j] = 0.f;

    gemm_tile<256>(XE, WT, acc, tx, ty);

    // epilogue: bias + silu + scatter-add
    #pragma unroll
    for (int i = 0; i < 8; ++i) {
        int e = (i < 4) ? (ty * 4 + i) : (128 + ty * 4 + i - 4);
        int r = sr[e];
        if (r < 0) continue;
        float* dst = g_agg + (size_t)r * D;
        #pragma unroll
        for (int j = 0; j < 8; ++j) {
            int d = (j < 4) ? (tx * 4 + j) : (64 + tx * 4 + j - 4);
            atomicAdd(dst + d, silu_f(acc[i][j] + sb2[d]));
        }
    }
}

// ----------------------------------------------------------------------------
// T = silu([h, agg] @ U1.T + c1)    (U1 is [128, 256]; two K-phases)
// ----------------------------------------------------------------------------
__global__ __launch_bounds__(256, 1)
void node_c1_kernel(const float* __restrict__ h, const float* __restrict__ U1,
                    const float* __restrict__ c1, int N)
{
    extern __shared__ float sm[];
    float (*XE)[132] = (float (*)[132])sm;
    float (*WT)[132] = (float (*)[132])(sm + 128 * 132);
    float* sc1 = sm + 2 * 128 * 132;

    const int tid = threadIdx.x;
    const int n0  = blockIdx.x * 128;
    if (tid < 128) sc1[tid] = c1[tid];

    const int tx = tid & 15, ty = tid >> 4;
    float acc[8][8];
    #pragma unroll
    for (int i = 0; i < 8; ++i)
        #pragma unroll
        for (int j = 0; j < 8; ++j) acc[i][j] = 0.f;

    for (int ph = 0; ph < 2; ++ph) {
        if (ph) __syncthreads();
        const float* src = ph ? g_agg : h;
        for (int i = tid; i < 128 * 128; i += 256) {
            int d = i >> 7, k = i & 127;
            WT[k][d] = U1[d * 256 + ph * 128 + k];
        }
        for (int i = tid; i < 128 * 32; i += 256) {
            int e = i >> 5, d4 = (i & 31) << 2;
            int n = n0 + e;
            float4 v = make_float4(0.f, 0.f, 0.f, 0.f);
            if (n < N) v = *(const float4*)(src + (size_t)n * D + d4);
            *(float4*)&XE[e][d4] = v;
        }
        __syncthreads();
        gemm_tile<128>(XE, WT, acc, tx, ty);
    }

    #pragma unroll
    for (int i = 0; i < 8; ++i) {
        int e = (i < 4) ? (ty * 4 + i) : (64 + ty * 4 + i - 4);
        int n = n0 + e;
        if (n >= N) continue;
        float* dst = g_T + (size_t)n * D;
        #pragma unroll
        for (int j = 0; j < 8; ++j) {
            int d = (j < 4) ? (tx * 4 + j) : (64 + tx * 4 + j - 4);
            dst[d] = silu_f(acc[i][j] + sc1[d]);
        }
    }
}

// ----------------------------------------------------------------------------
// out = h + T @ U2.T + c2
// ----------------------------------------------------------------------------
__global__ __launch_bounds__(256, 1)
void node_c2_kernel(const float* __restrict__ h, const float* __restrict__ U2,
                    const float* __restrict__ c2, float* __restrict__ out, int N)
{
    extern __shared__ float sm[];
    float (*XE)[132] = (float (*)[132])sm;
    float (*WT)[132] = (float (*)[132])(sm + 128 * 132);
    float* sc2 = sm + 2 * 128 * 132;

    const int tid = threadIdx.x;
    const int n0  = blockIdx.x * 128;
    if (tid < 128) sc2[tid] = c2[tid];

    for (int i = tid; i < 128 * 128; i += 256) {
        int d = i >> 7, k = i & 127;
        WT[k][d] = U2[i];
    }
    for (int i = tid; i < 128 * 32; i += 256) {
        int e = i >> 5, d4 = (i & 31) << 2;
        int n = n0 + e;
        float4 v = make_float4(0.f, 0.f, 0.f, 0.f);
        if (n < N) v = *(const float4*)(g_T + (size_t)n * D + d4);
        *(float4*)&XE[e][d4] = v;
    }
    __syncthreads();

    const int tx = tid & 15, ty = tid >> 4;
    float acc[8][8];
    #pragma unroll
    for (int i = 0; i < 8; ++i)
        #pragma unroll
        for (int j = 0; j < 8; ++j) acc[i][j] = 0.f;

    gemm_tile<128>(XE, WT, acc, tx, ty);

    #pragma unroll
    for (int i = 0; i < 8; ++i) {
        int e = (i < 4) ? (ty * 4 + i) : (64 + ty * 4 + i - 4);
        int n = n0 + e;
        if (n >= N) continue;
        const float* hp = h + (size_t)n * D;
        float* op = out + (size_t)n * D;
        float4 h0 = *(const float4*)(hp + tx * 4);
        float4 h1 = *(const float4*)(hp + 64 + tx * 4);
        float4 v0, v1;
        v0.x = h0.x + acc[i][0] + sc2[tx * 4 + 0];
        v0.y = h0.y + acc[i][1] + sc2[tx * 4 + 1];
        v0.z = h0.z + acc[i][2] + sc2[tx * 4 + 2];
        v0.w = h0.w + acc[i][3] + sc2[tx * 4 + 3];
        v1.x = h1.x + acc[i][4] + sc2[64 + tx * 4 + 0];
        v1.y = h1.y + acc[i][5] + sc2[64 + tx * 4 + 1];
        v1.z = h1.z + acc[i][6] + sc2[64 + tx * 4 + 2];
        v1.w = h1.w + acc[i][7] + sc2[64 + tx * 4 + 3];
        *(float4*)(op + tx * 4)      = v0;
        *(float4*)(op + 64 + tx * 4) = v1;
    }
}

// ----------------------------------------------------------------------------
extern "C" void kernel_launch(void* const* d_in, const int* in_sizes, int n_in,
                              void* d_out, int out_size)
{
    const float*     h      = (const float*)d_in[0];
    const float*     coords = (const float*)d_in[1];
    const void*      ei     = d_in[2];
    const float*     W1     = (const float*)d_in[3];
    const float*     b1     = (const float*)d_in[4];
    const float*     W2     = (const float*)d_in[5];
    const float*     b2     = (const float*)d_in[6];
    const float*     U1     = (const float*)d_in[7];
    const float*     c1     = (const float*)d_in[8];
    const float*     U2     = (const float*)d_in[9];
    const float*     c2     = (const float*)d_in[10];
    float*           out    = (float*)d_out;

    const int N = in_sizes[0] / D;
    const int E = in_sizes[2] / 2;

    const size_t SMEM_EDGE = (size_t)(256 * 132 + 128 * 132 + 3 * 128 + 256) * 4
                           + 2 * 256 * 4;                       // ~202.5 KB
    const size_t SMEM_NODE = (size_t)(2 * 128 * 132 + 128) * 4; // ~132.5 KB

    cudaFuncSetAttribute(edge_kernel,    cudaFuncAttributeMaxDynamicSharedMemorySize, (int)SMEM_EDGE);
    cudaFuncSetAttribute(nodeAB_kernel,  cudaFuncAttributeMaxDynamicSharedMemorySize, (int)SMEM_NODE);
    cudaFuncSetAttribute(node_c1_kernel, cudaFuncAttributeMaxDynamicSharedMemorySize, (int)SMEM_NODE);
    cudaFuncSetAttribute(node_c2_kernel, cudaFuncAttributeMaxDynamicSharedMemorySize, (int)SMEM_NODE);

    const int nTiles = (N + 127) / 128;

    // 0) detect edge_index dtype (int32 vs int64)
    detect_idx_kernel<<<1, 256>>>((const int*)ei, E);

    // 1) zero aggregation buffer
    int n4 = N * (D / 4);
    zero_agg_kernel<<<(n4 + 255) / 256, 256>>>(n4);

    // 2) per-node layer-1 precompute (A, B halves)
    nodeAB_kernel<<<dim3(nTiles, 2), 256, SMEM_NODE>>>(h, W1, N);

    // 3) edge MLP + scatter
    edge_kernel<<<(E + 255) / 256, 512, SMEM_EDGE>>>(coords, ei, W1, b1, W2, b2, E);

    // 4) node update layer 1
    node_c1_kernel<<<nTiles, 256, SMEM_NODE>>>(h, U1, c1, N);

    // 5) node update layer 2 + residual
    node_c2_kernel<<<nTiles, 256, SMEM_NODE>>>(h, U2, c2, out, N);
}

// round 3
// speedup vs baseline: 1.1418x; 1.1418x over previous
#include <cuda_runtime.h>

#define D 128
#define NMAX 50000

typedef unsigned long long u64;

// ---- scratch (static device globals; no allocations allowed) ----
__device__ float g_A  [(size_t)NMAX * D];   // h @ W1a.T
__device__ float g_B  [(size_t)NMAX * D];   // h @ W1b.T
__device__ float g_agg[(size_t)NMAX * D];   // scatter-add target
__device__ float g_T  [(size_t)NMAX * D];   // silu(u_in @ U1.T + c1)
__device__ int   g_is64;                    // edge_index dtype flag

__device__ __forceinline__ float silu_f(float v) {
    return v / (1.0f + __expf(-v));
}

__device__ __forceinline__ u64 pack2(float lo, float hi) {
    u64 r;
    asm("mov.b64 %0, {%1, %2};" : "=l"(r) : "f"(lo), "f"(hi));
    return r;
}
__device__ __forceinline__ float2 unpack2(u64 v) {
    float2 r;
    asm("mov.b64 {%0, %1}, %2;" : "=f"(r.x), "=f"(r.y) : "l"(v));
    return r;
}
__device__ __forceinline__ void ffma2(u64& d, u64 a, u64 b) {
    asm("fma.rn.f32x2 %0, %1, %2, %0;" : "+l"(d) : "l"(a), "l"(b));
}
__device__ __forceinline__ void red_v4(float* p, float a, float b, float c, float d) {
    asm volatile("red.global.add.v4.f32 [%0], {%1, %2, %3, %4};"
                 :: "l"(p), "f"(a), "f"(b), "f"(c), "f"(d) : "memory");
}

// ----------------------------------------------------------------------------
// Detect whether edge_index is int64 or int32 (odd 32-bit words all zero <=> int64).
// ----------------------------------------------------------------------------
__global__ void detect_idx_kernel(const int* __restrict__ ei32, int E)
{
    __shared__ int any_nz;
    if (threadIdx.x == 0) any_nz = 0;
    __syncthreads();
    int samples = min(1024, E);
    for (int i = threadIdx.x; i < samples; i += blockDim.x)
        if (ei32[2 * i + 1] != 0) any_nz = 1;
    __syncthreads();
    if (threadIdx.x == 0) g_is64 = (any_nz == 0) ? 1 : 0;
}

__device__ __forceinline__ void load_edge(const void* ei, int E, int e, int is64,
                                          int& s, int& r)
{
    if (is64) {
        s = (int)((const long long*)ei)[e];
        r = (int)((const long long*)ei)[(size_t)E + e];
    } else {
        s = ((const int*)ei)[e];
        r = ((const int*)ei)[E + e];
    }
}

// ----------------------------------------------------------------------------
// 8x8 register-tiled fp32 GEMM core using packed fp32x2 FMA (fma.rn.f32x2).
// Pairing is along the output-column (j) axis: acc2[i][jp] holds cols
// (db+2jp, db+2jp+1) for jp<2 and (64+db+2jp-4...) for jp>=2.
// Weight float4s reinterpret directly as two u64 f32x2 lanes; x values are
// warp-broadcast scalars packed once per row per k.
// ----------------------------------------------------------------------------
template<int ER>
__device__ __forceinline__ void gemm_tile(const float (*__restrict__ XE)[132],
                                          const float (*__restrict__ WT)[132],
                                          u64 (&acc2)[8][4], int tx, int ty)
{
    const int eb = ty * 4, db = tx * 4;
    #pragma unroll 4
    for (int k = 0; k < 128; ++k) {
        u64 xa2[8];
        #pragma unroll
        for (int i = 0; i < 4; ++i) {
            float x0 = XE[eb + i][k];
            float x1 = XE[ER / 2 + eb + i][k];
            xa2[i]     = pack2(x0, x0);
            xa2[4 + i] = pack2(x1, x1);
        }
        ulonglong2 w0 = *(const ulonglong2*)&WT[k][db];        // cols db..db+3
        ulonglong2 w1 = *(const ulonglong2*)&WT[k][64 + db];   // cols 64+db..+3
        u64 wv[4] = {w0.x, w0.y, w1.x, w1.y};
        #pragma unroll
        for (int i = 0; i < 8; ++i)
            #pragma unroll
            for (int jp = 0; jp < 4; ++jp)
                ffma2(acc2[i][jp], xa2[i], wv[jp]);
    }
}

// ----------------------------------------------------------------------------
__global__ void zero_agg_kernel(int n4) {
    int i = blockIdx.x * blockDim.x + threadIdx.x;
    if (i < n4) ((float4*)g_agg)[i] = make_float4(0.f, 0.f, 0.f, 0.f);
}

// ----------------------------------------------------------------------------
// A = h @ W1[:, :128].T ; B = h @ W1[:, 128:256].T   (blockIdx.y selects half)
// ----------------------------------------------------------------------------
__global__ __launch_bounds__(256, 1)
void nodeAB_kernel(const float* __restrict__ h, const float* __restrict__ W1, int N)
{
    extern __shared__ float sm[];
    float (*XE)[132] = (float (*)[132])sm;                 // 128 x 132
    float (*WT)[132] = (float (*)[132])(sm + 128 * 132);   // 128 x 132

    const int tid  = threadIdx.x;
    const int n0   = blockIdx.x * 128;
    const int half = blockIdx.y;

    for (int i = tid; i < 128 * 128; i += 256) {
        int d = i >> 7, k = i & 127;
        WT[k][d] = W1[d * 257 + half * 128 + k];
    }
    for (int i = tid; i < 128 * 32; i += 256) {
        int e = i >> 5, d4 = (i & 31) << 2;
        int n = n0 + e;
        float4 v = make_float4(0.f, 0.f, 0.f, 0.f);
        if (n < N) v = *(const float4*)(h + (size_t)n * D + d4);
        *(float4*)&XE[e][d4] = v;
    }
    __syncthreads();

    const int tx = tid & 15, ty = tid >> 4;
    u64 acc2[8][4];
    #pragma unroll
    for (int i = 0; i < 8; ++i)
        #pragma unroll
        for (int j = 0; j < 4; ++j) acc2[i][j] = 0ull;

    gemm_tile<128>(XE, WT, acc2, tx, ty);

    float* outp = half ? g_B : g_A;
    #pragma unroll
    for (int i = 0; i < 8; ++i) {
        int e = (i < 4) ? (ty * 4 + i) : (64 + ty * 4 + i - 4);
        int n = n0 + e;
        if (n >= N) continue;
        float2 p0 = unpack2(acc2[i][0]), p1 = unpack2(acc2[i][1]);
        float2 p2 = unpack2(acc2[i][2]), p3 = unpack2(acc2[i][3]);
        *(float4*)(outp + (size_t)n * D + tx * 4)      = make_float4(p0.x, p0.y, p1.x, p1.y);
        *(float4*)(outp + (size_t)n * D + 64 + tx * 4) = make_float4(p2.x, p2.y, p3.x, p3.y);
    }
}

// ----------------------------------------------------------------------------
// Edge kernel: layer-1 collapsed gather + silu, layer-2 GEMM (fp32x2),
// silu + vectorized red.global.add.v4 scatter.
// ----------------------------------------------------------------------------
__global__ __launch_bounds__(512, 1)
void edge_kernel(const float* __restrict__ coords,
                 const void* __restrict__ ei,
                 const float* __restrict__ W1,
                 const float* __restrict__ b1,
                 const float* __restrict__ W2,
                 const float* __restrict__ b2,
                 int E)
{
    extern __shared__ float sm[];
    float (*XE)[132] = (float (*)[132])sm;                       // 256 x 132
    float (*WT)[132] = (float (*)[132])(sm + 256 * 132);         // 128 x 132
    float* sw1c  = sm + 256 * 132 + 128 * 132;                   // 128
    float* sb1   = sw1c + 128;                                   // 128
    float* sb2   = sb1 + 128;                                    // 128
    float* sdist = sb2 + 128;                                    // 256
    int*   sr    = (int*)(sdist + 256);                          // 256
    int*   ss    = sr + 256;                                     // 256

    const int tid = threadIdx.x;
    const int e0  = blockIdx.x * 256;
    const int is64 = g_is64;

    // stage W2 k-major
    for (int i = tid; i < 128 * 128; i += 512) {
        int d = i >> 7, k = i & 127;
        WT[k][d] = W2[i];
    }
    if (tid < 128) {
        sb1[tid]  = b1[tid];
        sb2[tid]  = b2[tid];
        sw1c[tid] = W1[tid * 257 + 256];
    }
    if (tid < 256) {
        int e = e0 + tid;
        if (e < E) {
            int s, r;
            load_edge(ei, E, e, is64, s, r);
            ss[tid] = s;
            sr[tid] = r;
            float dx = coords[s * 3 + 0] - coords[r * 3 + 0];
            float dy = coords[s * 3 + 1] - coords[r * 3 + 1];
            float dz = coords[s * 3 + 2] - coords[r * 3 + 2];
            sdist[tid] = sqrtf(dx * dx + dy * dy + dz * dz);
        } else {
            ss[tid] = 0; sr[tid] = -1; sdist[tid] = 0.f;
        }
    }
    __syncthreads();

    // stage 1: gather + collapsed layer-1 + silu
    for (int i = tid; i < 256 * 32; i += 512) {
        int e = i >> 5, d4 = (i & 31) << 2;
        int rr = sr[e]; if (rr < 0) rr = 0;
        const float4 a = *(const float4*)(g_A + (size_t)ss[e] * D + d4);
        const float4 b = *(const float4*)(g_B + (size_t)rr    * D + d4);
        float dist = sdist[e];
        float4 o;
        o.x = silu_f(a.x + b.x + dist * sw1c[d4 + 0] + sb1[d4 + 0]);
        o.y = silu_f(a.y + b.y + dist * sw1c[d4 + 1] + sb1[d4 + 1]);
        o.z = silu_f(a.z + b.z + dist * sw1c[d4 + 2] + sb1[d4 + 2]);
        o.w = silu_f(a.w + b.w + dist * sw1c[d4 + 3] + sb1[d4 + 3]);
        *(float4*)&XE[e][d4] = o;
    }
    __syncthreads();

    // stage 2: layer-2 GEMM
    const int tx = tid & 15, ty = tid >> 4;
    u64 acc2[8][4];
    #pragma unroll
    for (int i = 0; i < 8; ++i)
        #pragma unroll
        for (int j = 0; j < 4; ++j) acc2[i][j] = 0ull;

    gemm_tile<256>(XE, WT, acc2, tx, ty);

    // epilogue: bias + silu + vectorized scatter-add
    const int db = tx * 4;
    #pragma unroll
    for (int i = 0; i < 8; ++i) {
        int e = (i < 4) ? (ty * 4 + i) : (128 + ty * 4 + i - 4);
        int r = sr[e];
        if (r < 0) continue;
        float* dst = g_agg + (size_t)r * D;
        float2 p0 = unpack2(acc2[i][0]), p1 = unpack2(acc2[i][1]);
        float2 p2 = unpack2(acc2[i][2]), p3 = unpack2(acc2[i][3]);
        red_v4(dst + db,
               silu_f(p0.x + sb2[db + 0]), silu_f(p0.y + sb2[db + 1]),
               silu_f(p1.x + sb2[db + 2]), silu_f(p1.y + sb2[db + 3]));
        red_v4(dst + 64 + db,
               silu_f(p2.x + sb2[64 + db + 0]), silu_f(p2.y + sb2[64 + db + 1]),
               silu_f(p3.x + sb2[64 + db + 2]), silu_f(p3.y + sb2[64 + db + 3]));
    }
}

// ----------------------------------------------------------------------------
// T = silu([h, agg] @ U1.T + c1)    (U1 is [128, 256]; two K-phases)
// ----------------------------------------------------------------------------
__global__ __launch_bounds__(256, 1)
void node_c1_kernel(const float* __restrict__ h, const float* __restrict__ U1,
                    const float* __restrict__ c1, int N)
{
    extern __shared__ float sm[];
    float (*XE)[132] = (float (*)[132])sm;
    float (*WT)[132] = (float (*)[132])(sm + 128 * 132);
    float* sc1 = sm + 2 * 128 * 132;

    const int tid = threadIdx.x;
    const int n0  = blockIdx.x * 128;
    if (tid < 128) sc1[tid] = c1[tid];

    const int tx = tid & 15, ty = tid >> 4;
    u64 acc2[8][4];
    #pragma unroll
    for (int i = 0; i < 8; ++i)
        #pragma unroll
        for (int j = 0; j < 4; ++j) acc2[i][j] = 0ull;

    for (int ph = 0; ph < 2; ++ph) {
        if (ph) __syncthreads();
        const float* src = ph ? g_agg : h;
        for (int i = tid; i < 128 * 128; i += 256) {
            int d = i >> 7, k = i & 127;
            WT[k][d] = U1[d * 256 + ph * 128 + k];
        }
        for (int i = tid; i < 128 * 32; i += 256) {
            int e = i >> 5, d4 = (i & 31) << 2;
            int n = n0 + e;
            float4 v = make_float4(0.f, 0.f, 0.f, 0.f);
            if (n < N) v = *(const float4*)(src + (size_t)n * D + d4);
            *(float4*)&XE[e][d4] = v;
        }
        __syncthreads();
        gemm_tile<128>(XE, WT, acc2, tx, ty);
    }

    const int db = tx * 4;
    #pragma unroll
    for (int i = 0; i < 8; ++i) {
        int e = (i < 4) ? (ty * 4 + i) : (64 + ty * 4 + i - 4);
        int n = n0 + e;
        if (n >= N) continue;
        float* dst = g_T + (size_t)n * D;
        float2 p0 = unpack2(acc2[i][0]), p1 = unpack2(acc2[i][1]);
        float2 p2 = unpack2(acc2[i][2]), p3 = unpack2(acc2[i][3]);
        *(float4*)(dst + db) = make_float4(
            silu_f(p0.x + sc1[db + 0]), silu_f(p0.y + sc1[db + 1]),
            silu_f(p1.x + sc1[db + 2]), silu_f(p1.y + sc1[db + 3]));
        *(float4*)(dst + 64 + db) = make_float4(
            silu_f(p2.x + sc1[64 + db + 0]), silu_f(p2.y + sc1[64 + db + 1]),
            silu_f(p3.x + sc1[64 + db + 2]), silu_f(p3.y + sc1[64 + db + 3]));
    }
}

// ----------------------------------------------------------------------------
// out = h + T @ U2.T + c2
// ----------------------------------------------------------------------------
__global__ __launch_bounds__(256, 1)
void node_c2_kernel(const float* __restrict__ h, const float* __restrict__ U2,
                    const float* __restrict__ c2, float* __restrict__ out, int N)
{
    extern __shared__ float sm[];
    float (*XE)[132] = (float (*)[132])sm;
    float (*WT)[132] = (float (*)[132])(sm + 128 * 132);
    float* sc2 = sm + 2 * 128 * 132;

    const int tid = threadIdx.x;
    const int n0  = blockIdx.x * 128;
    if (tid < 128) sc2[tid] = c2[tid];

    for (int i = tid; i < 128 * 128; i += 256) {
        int d = i >> 7, k = i & 127;
        WT[k][d] = U2[i];
    }
    for (int i = tid; i < 128 * 32; i += 256) {
        int e = i >> 5, d4 = (i & 31) << 2;
        int n = n0 + e;
        float4 v = make_float4(0.f, 0.f, 0.f, 0.f);
        if (n < N) v = *(const float4*)(g_T + (size_t)n * D + d4);
        *(float4*)&XE[e][d4] = v;
    }
    __syncthreads();

    const int tx = tid & 15, ty = tid >> 4;
    u64 acc2[8][4];
    #pragma unroll
    for (int i = 0; i < 8; ++i)
        #pragma unroll
        for (int j = 0; j < 4; ++j) acc2[i][j] = 0ull;

    gemm_tile<128>(XE, WT, acc2, tx, ty);

    const int db = tx * 4;
    #pragma unroll
    for (int i = 0; i < 8; ++i) {
        int e = (i < 4) ? (ty * 4 + i) : (64 + ty * 4 + i - 4);
        int n = n0 + e;
        if (n >= N) continue;
        const float* hp = h + (size_t)n * D;
        float* op = out + (size_t)n * D;
        float4 h0 = *(const float4*)(hp + db);
        float4 h1 = *(const float4*)(hp + 64 + db);
        float2 p0 = unpack2(acc2[i][0]), p1 = unpack2(acc2[i][1]);
        float2 p2 = unpack2(acc2[i][2]), p3 = unpack2(acc2[i][3]);
        *(float4*)(op + db) = make_float4(
            h0.x + p0.x + sc2[db + 0], h0.y + p0.y + sc2[db + 1],
            h0.z + p1.x + sc2[db + 2], h0.w + p1.y + sc2[db + 3]);
        *(float4*)(op + 64 + db) = make_float4(
            h1.x + p2.x + sc2[64 + db + 0], h1.y + p2.y + sc2[64 + db + 1],
            h1.z + p3.x + sc2[64 + db + 2], h1.w + p3.y + sc2[64 + db + 3]);
    }
}

// ----------------------------------------------------------------------------
extern "C" void kernel_launch(void* const* d_in, const int* in_sizes, int n_in,
                              void* d_out, int out_size)
{
    const float*     h      = (const float*)d_in[0];
    const float*     coords = (const float*)d_in[1];
    const void*      ei     = d_in[2];
    const float*     W1     = (const float*)d_in[3];
    const float*     b1     = (const float*)d_in[4];
    const float*     W2     = (const float*)d_in[5];
    const float*     b2     = (const float*)d_in[6];
    const float*     U1     = (const float*)d_in[7];
    const float*     c1     = (const float*)d_in[8];
    const float*     U2     = (const float*)d_in[9];
    const float*     c2     = (const float*)d_in[10];
    float*           out    = (float*)d_out;

    const int N = in_sizes[0] / D;
    const int E = in_sizes[2] / 2;

    const size_t SMEM_EDGE = (size_t)(256 * 132 + 128 * 132 + 3 * 128 + 256) * 4
                           + 2 * 256 * 4;                       // ~202.5 KB
    const size_t SMEM_NODE = (size_t)(2 * 128 * 132 + 128) * 4; // ~132.5 KB

    cudaFuncSetAttribute(edge_kernel,    cudaFuncAttributeMaxDynamicSharedMemorySize, (int)SMEM_EDGE);
    cudaFuncSetAttribute(nodeAB_kernel,  cudaFuncAttributeMaxDynamicSharedMemorySize, (int)SMEM_NODE);
    cudaFuncSetAttribute(node_c1_kernel, cudaFuncAttributeMaxDynamicSharedMemorySize, (int)SMEM_NODE);
    cudaFuncSetAttribute(node_c2_kernel, cudaFuncAttributeMaxDynamicSharedMemorySize, (int)SMEM_NODE);

    const int nTiles = (N + 127) / 128;

    // 0) detect edge_index dtype (int32 vs int64)
    detect_idx_kernel<<<1, 256>>>((const int*)ei, E);

    // 1) zero aggregation buffer
    int n4 = N * (D / 4);
    zero_agg_kernel<<<(n4 + 255) / 256, 256>>>(n4);

    // 2) per-node layer-1 precompute (A, B halves)
    nodeAB_kernel<<<dim3(nTiles, 2), 256, SMEM_NODE>>>(h, W1, N);

    // 3) edge MLP + scatter
    edge_kernel<<<(E + 255) / 256, 512, SMEM_EDGE>>>(coords, ei, W1, b1, W2, b2, E);

    // 4) node update layer 1
    node_c1_kernel<<<nTiles, 256, SMEM_NODE>>>(h, U1, c1, N);

    // 5) node update layer 2 + residual
    node_c2_kernel<<<nTiles, 256, SMEM_NODE>>>(h, U2, c2, out, N);
}